// round 11
// baseline (speedup 1.0000x reference)
#include <cuda_runtime.h>
#include <cuda_bf16.h>

#define NN 262144
#define BB 4096
#define NEGV -1000000000.0f
#define XS 1032      // floats per warp x-block; 258 granules ≡ 2 (mod 8) → ng blocks on distinct bank groups
#define HS 66        // h / W2t row stride (floats)

typedef unsigned long long ull;

__device__ int g_starts[BB + 1];
__device__ float g_gb[BB * 64];   // precomputed glob@W1b + b1

// ---- fused prep: blocks [0,512) compute gb; blocks [512,768) compute seg starts ----
__global__ void __launch_bounds__(256) prep_kernel(
    const int* __restrict__ batch,
    const float* __restrict__ glob, const float* __restrict__ W1,
    const float* __restrict__ b1)
{
    const int tid = threadIdx.x, w = tid >> 5, lane = tid & 31;
    if (blockIdx.x < 512) {
        __shared__ float sW1b[8192];
        {
            const float4* src = (const float4*)(W1 + 128 * 64);
            float4* dst = (float4*)sW1b;
            #pragma unroll
            for (int i = 0; i < 8; ++i) dst[tid + 256 * i] = src[tid + 256 * i];
        }
        const int b = blockIdx.x * 8 + w;
        float gl[4];
        #pragma unroll
        for (int i = 0; i < 4; ++i) gl[i] = glob[b * 128 + lane + 32 * i];
        float2 bv = *(const float2*)&b1[2 * lane];
        float g0 = bv.x, g1 = bv.y;
        __syncthreads();
        #pragma unroll 8
        for (int k = 0; k < 128; ++k) {
            float x = __shfl_sync(0xffffffffu, gl[k >> 5], k & 31);
            float2 wv = *(const float2*)&sW1b[k * 64 + 2 * lane];
            g0 = fmaf(x, wv.x, g0);
            g1 = fmaf(x, wv.y, g1);
        }
        *(float2*)&g_gb[b * 64 + 2 * lane] = make_float2(g0, g1);
    } else {
        const int sid = blockIdx.x - 512;
        const int i0 = sid * 1024 + tid * 4;
        int4 v = *(const int4*)&batch[i0];
        int prev = __shfl_up_sync(0xffffffffu, v.w, 1);
        if (lane == 0) prev = (i0 == 0) ? -1 : batch[i0 - 1];
        int c[4] = {v.x, v.y, v.z, v.w};
        int p = prev;
        #pragma unroll
        for (int t = 0; t < 4; ++t) {
            for (int b = p + 1; b <= c[t]; ++b) g_starts[b] = i0 + t;
            p = c[t];
        }
        if (i0 + 4 == NN) {
            for (int b = v.w + 1; b <= BB; ++b) g_starts[b] = NN;
        }
    }
}

// ---- packed f32x2 helpers ----
__device__ __forceinline__ ull pk2(float a, float b) {
    ull r;
    asm("mov.b64 %0, {%1, %2};" : "=l"(r) : "f"(a), "f"(b));
    return r;
}
__device__ __forceinline__ void upk2(ull v, float& a, float& b) {
    asm("mov.b64 {%0, %1}, %2;" : "=f"(a), "=f"(b) : "l"(v));
}
__device__ __forceinline__ ull fma2(ull a, ull b, ull c) {
    ull r;
    asm("fma.rn.f32x2 %0, %1, %2, %3;" : "=l"(r) : "l"(a), "l"(b), "l"(c));
    return r;
}

// Main kernel: CTA = 4 batches (one per warp for scan/gather/epilogue).
// Mainloop: warp w computes hidden slice [16w,16w+16) for ALL 32 CTA nodes
// → W1 traffic per warp is 8KB (64B/k) instead of 32KB.
__global__ void __launch_bounds__(128, 7) maneuver_kernel(
    const float* __restrict__ nf,
    const int* __restrict__ gmask, const int* __restrict__ mm,
    const float* __restrict__ W1,
    const float* __restrict__ W2, const float* __restrict__ b2,
    float* __restrict__ out)
{
    __shared__ float sx[4 * XS + 7 * HS];
    float* sW2t = sx + 4 * XS;
    const int tid  = threadIdx.x;
    const int w    = tid >> 5;
    const int lane = tid & 31;
    const int jp   = lane >> 2;   // hidden pair within slice (0..7)
    const int ng   = lane & 3;    // which warp-block of nodes (0..3)

    // stage W2 transposed (stride HS, conflict-free reads later)
    #pragma unroll
    for (int t = tid; t < 448; t += 128) {
        int d = t >> 6, j = t & 63;
        sW2t[d * HS + j] = __ldg(&W2[j * 7 + d]);
    }

    const int b = blockIdx.x * 4 + w;
    const int s = g_starts[b];
    const int e = g_starts[b + 1];

    // ---- find first <=8 selected nodes in [s, e) ----
    int cnt = 0;
    int my_node = -1;
    for (int base = s; base < e && cnt < 8; base += 32) {
        int i = base + lane;
        bool m = (i < e) && (gmask[i] != 0);
        unsigned bal = __ballot_sync(0xffffffffu, m);
        int ns = __popc(bal);
        int want = lane - cnt;
        if (lane < 8 && want >= 0 && want < ns) {
            unsigned mk = bal;
            #pragma unroll
            for (int t = 0; t < 7; ++t) if (t < want) mk &= (mk - 1u);
            my_node = base + (__ffs(mk) - 1);
        }
        cnt += ns;
    }
    const int V = cnt < 8 ? cnt : 8;

    // ---- gather this warp's 8 node rows as float4 (lane owns cols 4l..4l+3) ----
    const float4* nf4 = (const float4*)nf;
    float4 a[8];
    #pragma unroll
    for (int n = 0; n < 8; ++n) {
        int ni = __shfl_sync(0xffffffffu, my_node, n);
        a[n] = (ni >= 0) ? nf4[(size_t)ni * 32 + lane]
                         : make_float4(0.f, 0.f, 0.f, 0.f);
    }

    // gb init values: batch of node-block ng, hidden (16w+2jp, +1)
    const float2 gv = *(const float2*)&g_gb[(blockIdx.x * 4 + ng) * 64 + 16 * w + 2 * jp];

    // ---- transpose into this warp's x block: k-major, 8 floats per k ----
    {
        float* xw = sx + w * XS;
        #pragma unroll
        for (int j = 0; j < 4; ++j) {
            int k = 4 * lane + j;
            float* p = &xw[k * 8];
            ((float4*)p)[0] = make_float4(((const float*)&a[0])[j], ((const float*)&a[1])[j],
                                          ((const float*)&a[2])[j], ((const float*)&a[3])[j]);
            ((float4*)p)[1] = make_float4(((const float*)&a[4])[j], ((const float*)&a[5])[j],
                                          ((const float*)&a[6])[j], ((const float*)&a[7])[j]);
        }
    }
    __syncthreads();

    // ---- layer 1 mainloop: lane = (hidden pair jp of slice w) x (node block ng) ----
    ull acc[4][2];
    #pragma unroll
    for (int p = 0; p < 4; ++p) {
        acc[p][0] = pk2(gv.x, gv.x);
        acc[p][1] = pk2(gv.y, gv.y);
    }
    const float2* W1v = (const float2*)W1;
    const int jcol = 8 * w + jp;                 // float2 column index in W1 row
    const float* xng = sx + ng * XS;
    #pragma unroll 4
    for (int k = 0; k < 128; ++k) {
        float2 wv = __ldg(&W1v[k * 32 + jcol]);  // 64B per warp (4-lane broadcast)
        ull ww0 = pk2(wv.x, wv.x);
        ull ww1 = pk2(wv.y, wv.y);
        ulonglong2 xA = *(const ulonglong2*)&xng[k * 8];       // node pairs 0,1 of block ng
        ulonglong2 xB = *(const ulonglong2*)&xng[k * 8 + 4];   // node pairs 2,3
        acc[0][0] = fma2(xA.x, ww0, acc[0][0]);  acc[0][1] = fma2(xA.x, ww1, acc[0][1]);
        acc[1][0] = fma2(xA.y, ww0, acc[1][0]);  acc[1][1] = fma2(xA.y, ww1, acc[1][1]);
        acc[2][0] = fma2(xB.x, ww0, acc[2][0]);  acc[2][1] = fma2(xB.x, ww1, acc[2][1]);
        acc[3][0] = fma2(xB.y, ww0, acc[3][0]);  acc[3][1] = fma2(xB.y, ww1, acc[3][1]);
    }
    __syncthreads();   // all warps done reading x → safe to overwrite with h

    // ---- relu + h writeback: h[node][hidden], node = 8ng+2p(+1), hidden = 16w+2jp(+1) ----
    #pragma unroll
    for (int p = 0; p < 4; ++p) {
        float n0j0, n1j0, n0j1, n1j1;
        upk2(acc[p][0], n0j0, n1j0);
        upk2(acc[p][1], n0j1, n1j1);
        int n0 = 8 * ng + 2 * p;
        int jb = 16 * w + 2 * jp;
        *(float2*)&sx[n0 * HS + jb]       = make_float2(fmaxf(n0j0, 0.f), fmaxf(n0j1, 0.f));
        *(float2*)&sx[(n0 + 1) * HS + jb] = make_float2(fmaxf(n1j0, 0.f), fmaxf(n1j1, 0.f));
    }
    __syncthreads();   // h complete (cross-warp) + W2t visible

    // ---- layer 2 + mask + store: warp handles its own batch's 56 outputs ----
    #pragma unroll
    for (int pp = 0; pp < 2; ++pp) {
        int idx = pp * 32 + lane;
        if (idx < 56) {
            int n = idx / 7, d = idx - n * 7;
            float val = NEGV;
            if (n < V && mm[b * 56 + idx] != 0) {
                const float* hb = &sx[(8 * w + n) * HS];
                const float* wt = &sW2t[d * HS];
                ull acc2 = pk2(0.f, 0.f);
                #pragma unroll
                for (int j2 = 0; j2 < 32; ++j2)
                    acc2 = fma2(*(const ull*)&hb[2 * j2], *(const ull*)&wt[2 * j2], acc2);
                float s0, s1;
                upk2(acc2, s0, s1);
                val = s0 + s1 + __ldg(&b2[d]);
            }
            out[b * 56 + idx] = val;
        }
    }
}

extern "C" void kernel_launch(void* const* d_in, const int* in_sizes, int n_in,
                              void* d_out, int out_size) {
    const float* nf    = (const float*)d_in[0];
    const float* glob  = (const float*)d_in[1];
    const int*   gmask = (const int*)d_in[2];
    const int*   batch = (const int*)d_in[3];
    const int*   mm    = (const int*)d_in[4];
    const float* W1    = (const float*)d_in[5];
    const float* b1    = (const float*)d_in[6];
    const float* W2    = (const float*)d_in[7];
    const float* b2    = (const float*)d_in[8];
    float*       out   = (float*)d_out;

    prep_kernel<<<768, 256>>>(batch, glob, W1, b1);
    maneuver_kernel<<<BB / 4, 128>>>(nf, gmask, mm, W1, W2, b2, out);
}

// round 12
// speedup vs baseline: 1.2170x; 1.2170x over previous
#include <cuda_runtime.h>
#include <cuda_bf16.h>

#define NN 262144
#define BB 4096
#define NEGV -1000000000.0f

typedef unsigned long long ull;

__device__ int g_starts[BB + 1];
__device__ float g_gb[BB * 64];   // precomputed glob@W1b + b1

// ---- fused prep: blocks [0,512) compute gb; blocks [512,768) compute seg starts ----
__global__ void __launch_bounds__(256) prep_kernel(
    const int* __restrict__ batch,
    const float* __restrict__ glob, const float* __restrict__ W1,
    const float* __restrict__ b1)
{
    const int tid = threadIdx.x, w = tid >> 5, lane = tid & 31;
    if (blockIdx.x < 512) {
        // gb[b][j] = glob[b] @ W1[128:][:,j] + b1[j]; warp = batch, lane owns j=2l,2l+1
        __shared__ float sW1b[8192];
        __shared__ float sGlob[8 * 128];
        {
            const float4* src = (const float4*)(W1 + 128 * 64);
            float4* dst = (float4*)sW1b;
            #pragma unroll
            for (int i = 0; i < 8; ++i) dst[tid + 256 * i] = src[tid + 256 * i];
            // stage 8 batches' glob rows (1024 floats = 256 float4)
            const float4* gsrc = (const float4*)(glob + (size_t)blockIdx.x * 8 * 128);
            ((float4*)sGlob)[tid] = gsrc[tid];
        }
        const int b = blockIdx.x * 8 + w;
        float2 bv = *(const float2*)&b1[2 * lane];
        float g0 = bv.x, g1 = bv.y;
        __syncthreads();
        const float* xg = &sGlob[w * 128];
        #pragma unroll 8
        for (int k = 0; k < 128; ++k) {
            float x = xg[k];                              // LDS broadcast
            float2 wv = *(const float2*)&sW1b[k * 64 + 2 * lane];
            g0 = fmaf(x, wv.x, g0);
            g1 = fmaf(x, wv.y, g1);
        }
        *(float2*)&g_gb[b * 64 + 2 * lane] = make_float2(g0, g1);
    } else {
        // segment starts, 4 elements per thread (int4)
        const int sid = blockIdx.x - 512;
        const int i0 = sid * 1024 + tid * 4;
        int4 v = *(const int4*)&batch[i0];
        int prev = __shfl_up_sync(0xffffffffu, v.w, 1);
        if (lane == 0) prev = (i0 == 0) ? -1 : batch[i0 - 1];
        int c[4] = {v.x, v.y, v.z, v.w};
        int p = prev;
        #pragma unroll
        for (int t = 0; t < 4; ++t) {
            for (int b = p + 1; b <= c[t]; ++b) g_starts[b] = i0 + t;
            p = c[t];
        }
        if (i0 + 4 == NN) {
            for (int b = v.w + 1; b <= BB; ++b) g_starts[b] = NN;
        }
    }
}

// ---- packed f32x2 helpers ----
__device__ __forceinline__ ull pk2(float a, float b) {
    ull r;
    asm("mov.b64 %0, {%1, %2};" : "=l"(r) : "f"(a), "f"(b));
    return r;
}
__device__ __forceinline__ void upk2(ull v, float& a, float& b) {
    asm("mov.b64 {%0, %1}, %2;" : "=f"(a), "=f"(b) : "l"(v));
}
__device__ __forceinline__ ull fma2(ull a, ull b, ull c) {
    ull r;
    asm("fma.rn.f32x2 %0, %1, %2, %3;" : "=l"(r) : "l"(a), "l"(b), "l"(c));
    return r;
}

// Main kernel (R9 structure): warp = batch, W1 via L1, 16KB static smem/CTA.
__global__ void __launch_bounds__(128, 7) maneuver_kernel(
    const float* __restrict__ nf,
    const int* __restrict__ gmask, const int* __restrict__ mm,
    const float* __restrict__ W1,
    const float* __restrict__ W2, const float* __restrict__ b2,
    float* __restrict__ out)
{
    __shared__ float sxp_all[4 * 1024];
    const int tid  = threadIdx.x;
    const int w    = tid >> 5;
    const int lane = tid & 31;
    float* sxp = sxp_all + w * 1024;   // 128 k x 8 floats

    const int b = blockIdx.x * 4 + w;
    const int s = g_starts[b];
    const int e = g_starts[b + 1];

    // independent early loads: gb, maneuver mask, b2 (hide DRAM under scan+mainloop)
    float2 gv = *(const float2*)&g_gb[b * 64 + 2 * lane];
    int mm0 = mm[b * 56 + lane];
    int mm1 = (lane < 24) ? mm[b * 56 + 32 + lane] : 0;
    float b2v0 = __ldg(&b2[lane % 7]);

    // ---- find first <=8 selected nodes in [s, e) ----
    int cnt = 0;
    int my_node = -1;   // lanes 0..7 each own one node index
    for (int base = s; base < e && cnt < 8; base += 32) {
        int i = base + lane;
        bool m = (i < e) && (gmask[i] != 0);
        unsigned bal = __ballot_sync(0xffffffffu, m);
        int ns = __popc(bal);
        int want = lane - cnt;
        if (lane < 8 && want >= 0 && want < ns) {
            unsigned mk = bal;
            #pragma unroll
            for (int t = 0; t < 7; ++t) if (t < want) mk &= (mk - 1u);
            my_node = base + (__ffs(mk) - 1);
        }
        cnt += ns;
    }
    const int V = cnt < 8 ? cnt : 8;

    // ---- gather 8 node rows as float4 (lane owns cols 4l..4l+3) ----
    const float4* nf4 = (const float4*)nf;
    float4 a[8];
    #pragma unroll
    for (int n = 0; n < 8; ++n) {
        int ni = __shfl_sync(0xffffffffu, my_node, n);
        a[n] = (ni >= 0) ? nf4[(size_t)ni * 32 + lane]
                         : make_float4(0.f, 0.f, 0.f, 0.f);
    }

    // ---- transpose to smem: k = 4*lane + j, 8 floats per k ----
    #pragma unroll
    for (int j = 0; j < 4; ++j) {
        int k = 4 * lane + j;
        float* p = &sxp[k * 8];
        ((float4*)p)[0] = make_float4(((const float*)&a[0])[j], ((const float*)&a[1])[j],
                                      ((const float*)&a[2])[j], ((const float*)&a[3])[j]);
        ((float4*)p)[1] = make_float4(((const float*)&a[4])[j], ((const float*)&a[5])[j],
                                      ((const float*)&a[6])[j], ((const float*)&a[7])[j]);
    }
    __syncwarp();

    // ---- layer 1 mainloop: 8 nodes x 2 hidden per lane, W1 via L1 ----
    ull acc0[4], acc1[4];
    #pragma unroll
    for (int p = 0; p < 4; ++p) {
        acc0[p] = pk2(gv.x, gv.x);
        acc1[p] = pk2(gv.y, gv.y);
    }
    const float2* W1v = (const float2*)W1;
    #pragma unroll 4
    for (int k = 0; k < 128; ++k) {
        float2 wv = __ldg(&W1v[k * 32 + lane]);
        ull ww0 = pk2(wv.x, wv.x);
        ull ww1 = pk2(wv.y, wv.y);
        ulonglong2 xA = *(const ulonglong2*)&sxp[k * 8];       // pairs 0,1
        ulonglong2 xB = *(const ulonglong2*)&sxp[k * 8 + 4];   // pairs 2,3
        acc0[0] = fma2(xA.x, ww0, acc0[0]);  acc1[0] = fma2(xA.x, ww1, acc1[0]);
        acc0[1] = fma2(xA.y, ww0, acc0[1]);  acc1[1] = fma2(xA.y, ww1, acc1[1]);
        acc0[2] = fma2(xB.x, ww0, acc0[2]);  acc1[2] = fma2(xB.x, ww1, acc1[2]);
        acc0[3] = fma2(xB.y, ww0, acc0[3]);  acc1[3] = fma2(xB.y, ww1, acc1[3]);
    }

    // ---- relu, stash h (reuse sxp): h[n*66 + j] ----
    __syncwarp();
    #pragma unroll
    for (int p = 0; p < 4; ++p) {
        float hx0, hy0, hx1, hy1;
        upk2(acc0[p], hx0, hy0);   // hidden 2l : node 2p (x), node 2p+1 (y)
        upk2(acc1[p], hx1, hy1);   // hidden 2l+1
        sxp[(2 * p) * 66 + 2 * lane]         = fmaxf(hx0, 0.f);
        sxp[(2 * p) * 66 + 2 * lane + 1]     = fmaxf(hx1, 0.f);
        sxp[(2 * p + 1) * 66 + 2 * lane]     = fmaxf(hy0, 0.f);
        sxp[(2 * p + 1) * 66 + 2 * lane + 1] = fmaxf(hy1, 0.f);
    }
    __syncwarp();

    // ---- layer 2 + mask + store: 56 outputs ----
    #pragma unroll
    for (int p = 0; p < 2; ++p) {
        int idx = p * 32 + lane;
        int mv  = p == 0 ? mm0 : mm1;
        if (idx < 56) {
            int n = idx / 7, d = idx - n * 7;
            float val = NEGV;
            if (n < V && mv != 0) {
                float sum = (d == lane % 7) ? b2v0 : __ldg(&b2[d]);
                const float* hb = &sxp[n * 66];
                #pragma unroll
                for (int j = 0; j < 64; ++j)
                    sum = fmaf(hb[j], __ldg(&W2[j * 7 + d]), sum);
                val = sum;
            }
            out[b * 56 + idx] = val;
        }
    }
}

extern "C" void kernel_launch(void* const* d_in, const int* in_sizes, int n_in,
                              void* d_out, int out_size) {
    const float* nf    = (const float*)d_in[0];
    const float* glob  = (const float*)d_in[1];
    const int*   gmask = (const int*)d_in[2];
    const int*   batch = (const int*)d_in[3];
    const int*   mm    = (const int*)d_in[4];
    const float* W1    = (const float*)d_in[5];
    const float* b1    = (const float*)d_in[6];
    const float* W2    = (const float*)d_in[7];
    const float* b2    = (const float*)d_in[8];
    float*       out   = (float*)d_out;

    prep_kernel<<<768, 256>>>(batch, glob, W1, b1);
    maneuver_kernel<<<BB / 4, 128>>>(nf, gmask, mm, W1, W2, b2, out);
}

// round 13
// speedup vs baseline: 1.4757x; 1.2126x over previous
#include <cuda_runtime.h>
#include <cuda_bf16.h>

#define NN 262144
#define BB 4096
#define NEGV -1000000000.0f

typedef unsigned long long ull;

// ---- packed f32x2 helpers ----
__device__ __forceinline__ ull pk2(float a, float b) {
    ull r;
    asm("mov.b64 %0, {%1, %2};" : "=l"(r) : "f"(a), "f"(b));
    return r;
}
__device__ __forceinline__ void upk2(ull v, float& a, float& b) {
    asm("mov.b64 {%0, %1}, %2;" : "=f"(a), "=f"(b) : "l"(v));
}
__device__ __forceinline__ ull fma2(ull a, ull b, ull c) {
    ull r;
    asm("fma.rn.f32x2 %0, %1, %2, %3;" : "=l"(r) : "l"(a), "l"(b), "l"(c));
    return r;
}

// Single fused kernel: warp = batch.
//  - lower_bound(batch, b) via 32-ary warp search (4 ballot rounds)
//  - gb = glob[b]@W1[128:] + b1 inlined (packed fma2, W1 via L1)
//  - layer1 mainloop 8 nodes x 2 hidden/lane, layer2 epilogue
__global__ void __launch_bounds__(128, 7) maneuver_kernel(
    const float* __restrict__ nf, const float* __restrict__ glob,
    const int* __restrict__ gmask, const int* __restrict__ batch,
    const int* __restrict__ mm,
    const float* __restrict__ W1, const float* __restrict__ b1,
    const float* __restrict__ W2, const float* __restrict__ b2,
    float* __restrict__ out)
{
    __shared__ float sxp_all[4 * 1024];
    __shared__ float sglob_all[4 * 128];
    const int tid  = threadIdx.x;
    const int w    = tid >> 5;
    const int lane = tid & 31;
    float* sxp   = sxp_all + w * 1024;    // 128 k x 8 floats
    float* sgl   = sglob_all + w * 128;

    const int b = blockIdx.x * 4 + w;

    // independent early loads (hide DRAM): glob row, b1, masks
    float4 gl4 = ((const float4*)glob)[b * 32 + lane];
    float2 b1v = *(const float2*)&b1[2 * lane];
    int mm0 = mm[b * 56 + lane];
    int mm1 = (lane < 24) ? mm[b * 56 + 32 + lane] : 0;

    // ---- 32-ary lower_bound: s = first i with batch[i] >= b ----
    int lo = 0, hi = NN;
    while (hi - lo > 32) {
        int span = hi - lo;
        int pos = lo + (int)(((long long)span * (lane + 1)) >> 5);   // lanes 0..30 interior
        bool c = false;
        if (lane < 31 && pos < NN) c = (batch[pos] < b);
        unsigned bal = __ballot_sync(0xffffffffu, c);
        int t = __popc(bal);                 // lanes with batch[pos] < b (monotone prefix)
        int nlo = (t > 0) ? lo + (int)(((long long)span * t) >> 5) + 1 : lo;
        int nhi = (t < 31) ? lo + (int)(((long long)span * (t + 1)) >> 5) : hi;
        lo = nlo; hi = nhi;
    }
    {
        int pos = lo + lane;
        bool c = (pos < hi && pos < NN) ? (batch[pos] < b) : false;
        unsigned bal = __ballot_sync(0xffffffffu, c);
        lo = lo + __popc(bal);
    }
    const int s = lo;

    // stash glob row to smem for gb loop (LDS broadcast later)
    ((float4*)sgl)[lane] = gl4;

    // ---- scan for first <=8 selected nodes; batch[i]==b bounds the segment ----
    int cnt = 0;
    int my_node = -1;   // lanes 0..7 each own one node index
    int base = s;
    while (true) {
        int i = base + lane;
        int bt = (i < NN) ? batch[i] : 0x7fffffff;
        bool m = (bt == b) ? (gmask[i] != 0) : false;
        unsigned bal = __ballot_sync(0xffffffffu, m);
        int ns = __popc(bal);
        int want = lane - cnt;
        if (lane < 8 && want >= 0 && want < ns) {
            unsigned mk = bal;
            #pragma unroll
            for (int t = 0; t < 7; ++t) if (t < want) mk &= (mk - 1u);
            my_node = base + (__ffs(mk) - 1);
        }
        cnt += ns;
        bool over = (bt > b);
        if (cnt >= 8 || __ballot_sync(0xffffffffu, over)) break;
        base += 32;
    }
    const int V = cnt < 8 ? cnt : 8;

    // ---- gather 8 node rows as float4 (lane owns cols 4l..4l+3) ----
    const float4* nf4 = (const float4*)nf;
    float4 a[8];
    #pragma unroll
    for (int n = 0; n < 8; ++n) {
        int ni = __shfl_sync(0xffffffffu, my_node, n);
        a[n] = (ni >= 0) ? nf4[(size_t)ni * 32 + lane]
                         : make_float4(0.f, 0.f, 0.f, 0.f);
    }

    // ---- gb = glob[b] @ W1[128:] + b1 (lane owns hidden 2l, 2l+1), packed ----
    __syncwarp();   // sgl visible
    const float2* W1v = (const float2*)W1;
    ull accg = pk2(b1v.x, b1v.y);
    #pragma unroll 4
    for (int k4 = 0; k4 < 32; ++k4) {
        float4 xg = *(const float4*)&sgl[k4 * 4];   // LDS.128 broadcast
        #pragma unroll
        for (int j = 0; j < 4; ++j) {
            int k = 4 * k4 + j;
            float2 wv = __ldg(&W1v[(128 + k) * 32 + lane]);
            float x = (j == 0) ? xg.x : (j == 1) ? xg.y : (j == 2) ? xg.z : xg.w;
            accg = fma2(pk2(wv.x, wv.y), pk2(x, x), accg);
        }
    }
    float g0, g1;
    upk2(accg, g0, g1);

    // ---- transpose x to smem: k = 4*lane + j, 8 floats per k ----
    #pragma unroll
    for (int j = 0; j < 4; ++j) {
        int k = 4 * lane + j;
        float* p = &sxp[k * 8];
        ((float4*)p)[0] = make_float4(((const float*)&a[0])[j], ((const float*)&a[1])[j],
                                      ((const float*)&a[2])[j], ((const float*)&a[3])[j]);
        ((float4*)p)[1] = make_float4(((const float*)&a[4])[j], ((const float*)&a[5])[j],
                                      ((const float*)&a[6])[j], ((const float*)&a[7])[j]);
    }
    __syncwarp();

    // ---- layer 1 mainloop: 8 nodes x 2 hidden per lane, W1 via L1 ----
    ull acc0[4], acc1[4];
    #pragma unroll
    for (int p = 0; p < 4; ++p) {
        acc0[p] = pk2(g0, g0);
        acc1[p] = pk2(g1, g1);
    }
    #pragma unroll 4
    for (int k = 0; k < 128; ++k) {
        float2 wv = __ldg(&W1v[k * 32 + lane]);
        ull ww0 = pk2(wv.x, wv.x);
        ull ww1 = pk2(wv.y, wv.y);
        ulonglong2 xA = *(const ulonglong2*)&sxp[k * 8];       // pairs 0,1
        ulonglong2 xB = *(const ulonglong2*)&sxp[k * 8 + 4];   // pairs 2,3
        acc0[0] = fma2(xA.x, ww0, acc0[0]);  acc1[0] = fma2(xA.x, ww1, acc1[0]);
        acc0[1] = fma2(xA.y, ww0, acc0[1]);  acc1[1] = fma2(xA.y, ww1, acc1[1]);
        acc0[2] = fma2(xB.x, ww0, acc0[2]);  acc1[2] = fma2(xB.x, ww1, acc1[2]);
        acc0[3] = fma2(xB.y, ww0, acc0[3]);  acc1[3] = fma2(xB.y, ww1, acc1[3]);
    }

    // ---- relu, stash h (reuse sxp): h[n*66 + j] ----
    __syncwarp();
    #pragma unroll
    for (int p = 0; p < 4; ++p) {
        float hx0, hy0, hx1, hy1;
        upk2(acc0[p], hx0, hy0);   // hidden 2l : node 2p (x), node 2p+1 (y)
        upk2(acc1[p], hx1, hy1);   // hidden 2l+1
        sxp[(2 * p) * 66 + 2 * lane]         = fmaxf(hx0, 0.f);
        sxp[(2 * p) * 66 + 2 * lane + 1]     = fmaxf(hx1, 0.f);
        sxp[(2 * p + 1) * 66 + 2 * lane]     = fmaxf(hy0, 0.f);
        sxp[(2 * p + 1) * 66 + 2 * lane + 1] = fmaxf(hy1, 0.f);
    }
    __syncwarp();

    // ---- layer 2 + mask + store: 56 outputs ----
    #pragma unroll
    for (int p = 0; p < 2; ++p) {
        int idx = p * 32 + lane;
        int mv  = p == 0 ? mm0 : mm1;
        if (idx < 56) {
            int n = idx / 7, d = idx - n * 7;
            float val = NEGV;
            if (n < V && mv != 0) {
                float sum = __ldg(&b2[d]);
                const float* hb = &sxp[n * 66];
                #pragma unroll
                for (int j = 0; j < 64; ++j)
                    sum = fmaf(hb[j], __ldg(&W2[j * 7 + d]), sum);
                val = sum;
            }
            out[b * 56 + idx] = val;
        }
    }
}

extern "C" void kernel_launch(void* const* d_in, const int* in_sizes, int n_in,
                              void* d_out, int out_size) {
    const float* nf    = (const float*)d_in[0];
    const float* glob  = (const float*)d_in[1];
    const int*   gmask = (const int*)d_in[2];
    const int*   batch = (const int*)d_in[3];
    const int*   mm    = (const int*)d_in[4];
    const float* W1    = (const float*)d_in[5];
    const float* b1    = (const float*)d_in[6];
    const float* W2    = (const float*)d_in[7];
    const float* b2    = (const float*)d_in[8];
    float*       out   = (float*)d_out;

    maneuver_kernel<<<BB / 4, 128>>>(nf, glob, gmask, batch, mm, W1, b1, W2, b2, out);
}